// round 12
// baseline (speedup 1.0000x reference)
#include <cuda_runtime.h>
#include <cuda_fp16.h>

#define NN 50000
#define NE 600000
#define CAP 64            // bucket capacity per node (max degree ~28)
#define SCALE 1024.0f
#define INV_SCALE (1.0f / 1024.0f)

// ---------------- scratch (__device__ globals) -----------------------------
__device__ __half g_Zh[NN * 32];     // fp16: x @ (S * D1 Wd1 D2 Wd2)
__device__ __half g_Th[NN * 32];     // fp16: A @ Z
__device__ int    g_deg[NN];
__device__ int    g_bucket[NN * CAP];
__device__ uint2  g_WfragZ[8 * 4 * 32];   // collapsed-weight B fragments
__device__ float  g_c2[32];               // b1^T D2 Wd2

__device__ __forceinline__ unsigned s2u(const void* p) {
    return (unsigned)__cvta_generic_to_shared(p);
}
union H2U { __half2 h; unsigned u; };

// ---------------------------------------------------------------------------
__global__ void k_zero() {
    int i = blockIdx.x * 256 + threadIdx.x;
    if (i < NN) g_deg[i] = 0;
}

// ---------------------------------------------------------------------------
// k_wfrag: build collapsed weight W12 = S * diag(w1) Wd1 diag(w2) Wd2
// directly in MMA B-fragment layout, plus c2 = b1^T diag(w2) Wd2.
// One block of 1024 threads; entry i = ((kt*4)+nt)*32+lane, 1024 entries.
// ---------------------------------------------------------------------------
__global__ void k_wfrag(const float* __restrict__ w1, const float* __restrict__ Wd1,
                        const float* __restrict__ w2, const float* __restrict__ Wd2,
                        const float* __restrict__ b1) {
    int i = threadIdx.x;                 // 0..1023
    int lane = i & 31, nt = (i >> 5) & 3, kt = i >> 7;
    int g = lane >> 2, tg = lane & 3;
    int n = nt * 8 + g;
    int k0 = kt * 16 + tg * 2;

    // t2[m] = w2[m] * Wd2[m][n]
    float t2[64];
#pragma unroll 8
    for (int m = 0; m < 64; m++) t2[m] = w2[m] * Wd2[m * 32 + n];

    float v[4];
    int ks[4] = {k0, k0 + 1, k0 + 8, k0 + 9};
#pragma unroll
    for (int q = 0; q < 4; q++) {
        int k = ks[q];
        const float* wr = Wd1 + k * 64;
        float s = 0.f;
#pragma unroll 8
        for (int m = 0; m < 64; m++) s = fmaf(wr[m], t2[m], s);
        v[q] = s * w1[k] * SCALE;
    }
    H2U u0, u1;
    u0.h = __floats2half2_rn(v[0], v[1]);
    u1.h = __floats2half2_rn(v[2], v[3]);
    g_WfragZ[i] = make_uint2(u0.u, u1.u);

    // c2[n] (threads 0..31)
    if (i < 32) {
        float s = 0.f;
#pragma unroll 8
        for (int m = 0; m < 64; m++)
            s = fmaf(b1[m] * w2[m], Wd2[m * 32 + i], s);
        g_c2[i] = s;
    }
}

// ---------------------------------------------------------------------------
// k_fill: one-pass adjacency build. deg doubles as cursor.
// ---------------------------------------------------------------------------
__global__ void k_fill(const int* __restrict__ src, const int* __restrict__ dst) {
    int i = blockIdx.x * 256 + threadIdx.x;
    if (i < NE / 4) {
        int4 s = reinterpret_cast<const int4*>(src)[i];
        int4 d = reinterpret_cast<const int4*>(dst)[i];
        int p;
        p = atomicAdd(&g_deg[d.x], 1); if (p < CAP) g_bucket[d.x * CAP + p] = s.x;
        p = atomicAdd(&g_deg[d.y], 1); if (p < CAP) g_bucket[d.y * CAP + p] = s.y;
        p = atomicAdd(&g_deg[d.z], 1); if (p < CAP) g_bucket[d.z * CAP + p] = s.z;
        p = atomicAdd(&g_deg[d.w], 1); if (p < CAP) g_bucket[d.w * CAP + p] = s.w;
    }
}

// ---------------------------------------------------------------------------
// k_dense: Z = x @ W12s  (K=128 -> N=32), HMMA, 64-node tiles, 782 blocks.
// 8 warps = 4 row-tiles x 2 col-halves (nt pairs).
// ---------------------------------------------------------------------------
__global__ void __launch_bounds__(256)
k_dense(const float* __restrict__ x) {
    __shared__ __half As[64 * 136];      // 17408 B
    int tid = threadIdx.x;
    int node0 = blockIdx.x * 64;
    for (int i = tid; i < 64 * 32; i += 256) {
        int r = i >> 5, c4 = i & 31;
        float4 v = make_float4(0.f, 0.f, 0.f, 0.f);
        if (node0 + r < NN)
            v = *reinterpret_cast<const float4*>(x + (size_t)(node0 + r) * 128 + c4 * 4);
        H2U u0, u1;
        u0.h = __floats2half2_rn(v.x, v.y);
        u1.h = __floats2half2_rn(v.z, v.w);
        *reinterpret_cast<uint2*>(As + r * 136 + c4 * 4) = make_uint2(u0.u, u1.u);
    }
    __syncthreads();

    int w = tid >> 5, lane = tid & 31, g = lane >> 2, tg = lane & 3;
    int warpRow = (w >> 1) * 16;
    int nthalf  = (w & 1) * 2;           // nt 0..1 or 2..3
    int lrow = warpRow + (lane & 15);
    int lkof = (lane >> 4) * 8;

    float acc[2][4] = {};
#pragma unroll
    for (int kt = 0; kt < 8; kt++) {
        unsigned a0, a1, a2, a3;
        unsigned addr = s2u(As + lrow * 136 + kt * 16 + lkof);
        asm volatile("ldmatrix.sync.aligned.m8n8.x4.shared.b16 {%0,%1,%2,%3}, [%4];"
                     : "=r"(a0), "=r"(a1), "=r"(a2), "=r"(a3) : "r"(addr));
#pragma unroll
        for (int nt = 0; nt < 2; nt++) {
            uint2 bb = __ldg(&g_WfragZ[((kt << 2) + nthalf + nt) * 32 + lane]);
            asm volatile(
                "mma.sync.aligned.m16n8k16.row.col.f32.f16.f16.f32 "
                "{%0,%1,%2,%3}, {%4,%5,%6,%7}, {%8,%9}, {%0,%1,%2,%3};"
                : "+f"(acc[nt][0]), "+f"(acc[nt][1]), "+f"(acc[nt][2]), "+f"(acc[nt][3])
                : "r"(a0), "r"(a1), "r"(a2), "r"(a3), "r"(bb.x), "r"(bb.y));
        }
    }

    int r0 = node0 + warpRow + g;
    int r1 = r0 + 8;
#pragma unroll
    for (int nt = 0; nt < 2; nt++) {
        int c = (nthalf + nt) * 8 + tg * 2;
        if (r0 < NN) {
            H2U u; u.h = __floats2half2_rn(acc[nt][0], acc[nt][1]);
            *reinterpret_cast<unsigned*>(g_Zh + (size_t)r0 * 32 + c) = u.u;
        }
        if (r1 < NN) {
            H2U u; u.h = __floats2half2_rn(acc[nt][2], acc[nt][3]);
            *reinterpret_cast<unsigned*>(g_Zh + (size_t)r1 * 32 + c) = u.u;
        }
    }
}

// ---------------------------------------------------------------------------
// half2 accumulation helper
// ---------------------------------------------------------------------------
__device__ __forceinline__ void hacc(__half2 a[4], uint4 v) {
    __half2* h = reinterpret_cast<__half2*>(&v);
    a[0] = __hadd2(a[0], h[0]);
    a[1] = __hadd2(a[1], h[1]);
    a[2] = __hadd2(a[2], h[2]);
    a[3] = __hadd2(a[3], h[3]);
}

// ---------------------------------------------------------------------------
// gather1: T = A@Z  (32-dim). 8 nodes/warp, 4 lanes x 8 halves.
// ---------------------------------------------------------------------------
__global__ void __launch_bounds__(256)
k_gather1() {
    int gw = (blockIdx.x * 256 + threadIdx.x) >> 5;
    int lane = threadIdx.x & 31;
    int sub = lane >> 2, sl = lane & 3;
    int node = gw * 8 + sub;
    if (node >= NN) return;

    int n = g_deg[node]; if (n > CAP) n = CAP;
    const int* bkt = g_bucket + (size_t)node * CAP;
    __half2 z = __float2half2_rn(0.f);
    __half2 s0[4] = {z, z, z, z}, s1[4] = {z, z, z, z};
    __half2 s2[4] = {z, z, z, z}, s3[4] = {z, z, z, z};

    int j = 0;
    for (; j + 4 <= n; j += 4) {
        int4 idx = *reinterpret_cast<const int4*>(bkt + j);
        hacc(s0, *reinterpret_cast<const uint4*>(g_Zh + (size_t)idx.x * 32 + sl * 8));
        hacc(s1, *reinterpret_cast<const uint4*>(g_Zh + (size_t)idx.y * 32 + sl * 8));
        hacc(s2, *reinterpret_cast<const uint4*>(g_Zh + (size_t)idx.z * 32 + sl * 8));
        hacc(s3, *reinterpret_cast<const uint4*>(g_Zh + (size_t)idx.w * 32 + sl * 8));
    }
    for (; j < n; j++)
        hacc(s0, *reinterpret_cast<const uint4*>(g_Zh + (size_t)bkt[j] * 32 + sl * 8));

    // merge slots in fp32, pack to fp16
    H2U p[4];
#pragma unroll
    for (int q = 0; q < 4; q++) {
        float2 f  = __half22float2(s0[q]);
        float2 t1 = __half22float2(s1[q]);
        float2 t2 = __half22float2(s2[q]);
        float2 t3 = __half22float2(s3[q]);
        p[q].h = __floats2half2_rn(f.x + t1.x + t2.x + t3.x,
                                   f.y + t1.y + t2.y + t3.y);
    }
    *reinterpret_cast<uint4*>(g_Th + (size_t)node * 32 + sl * 8) =
        make_uint4(p[0].u, p[1].u, p[2].u, p[3].u);
}

// ---------------------------------------------------------------------------
// gather2 + head + softmax.
// g2 = (A@T)/S + deg*c2 + b2;  logits = g2@Wout + bout; softmax.
// 8 nodes/warp, 4 lanes x 8 halves.
// ---------------------------------------------------------------------------
__global__ void __launch_bounds__(256)
k_gather2_final(const float* __restrict__ b2,
                const float* __restrict__ Wout,
                const float* __restrict__ bout,
                float* __restrict__ out) {
    int gw = (blockIdx.x * 256 + threadIdx.x) >> 5;
    int lane = threadIdx.x & 31;
    int sub = lane >> 2, sl = lane & 3;
    int node = gw * 8 + sub;
    if (node >= NN) return;

    int deg = g_deg[node];
    int n = deg; if (n > CAP) n = CAP;
    const int* bkt = g_bucket + (size_t)node * CAP;
    __half2 z = __float2half2_rn(0.f);
    __half2 s0[4] = {z, z, z, z}, s1[4] = {z, z, z, z};
    __half2 s2[4] = {z, z, z, z}, s3[4] = {z, z, z, z};

    int j = 0;
    for (; j + 4 <= n; j += 4) {
        int4 idx = *reinterpret_cast<const int4*>(bkt + j);
        hacc(s0, *reinterpret_cast<const uint4*>(g_Th + (size_t)idx.x * 32 + sl * 8));
        hacc(s1, *reinterpret_cast<const uint4*>(g_Th + (size_t)idx.y * 32 + sl * 8));
        hacc(s2, *reinterpret_cast<const uint4*>(g_Th + (size_t)idx.z * 32 + sl * 8));
        hacc(s3, *reinterpret_cast<const uint4*>(g_Th + (size_t)idx.w * 32 + sl * 8));
    }
    for (; j < n; j++)
        hacc(s0, *reinterpret_cast<const uint4*>(g_Th + (size_t)bkt[j] * 32 + sl * 8));

    float fdeg = (float)deg;
    float4 bL = __ldg(reinterpret_cast<const float4*>(b2 + sl * 8));
    float4 bH = __ldg(reinterpret_cast<const float4*>(b2 + sl * 8 + 4));
    float4 cL = *reinterpret_cast<const float4*>(g_c2 + sl * 8);
    float4 cH = *reinterpret_cast<const float4*>(g_c2 + sl * 8 + 4);

    float h[8];
#pragma unroll
    for (int q = 0; q < 4; q++) {
        float2 f  = __half22float2(s0[q]);
        float2 t1 = __half22float2(s1[q]);
        float2 t2 = __half22float2(s2[q]);
        float2 t3 = __half22float2(s3[q]);
        h[q * 2]     = (f.x + t1.x + t2.x + t3.x) * INV_SCALE;
        h[q * 2 + 1] = (f.y + t1.y + t2.y + t3.y) * INV_SCALE;
    }
    h[0] += fdeg * cL.x + bL.x; h[1] += fdeg * cL.y + bL.y;
    h[2] += fdeg * cL.z + bL.z; h[3] += fdeg * cL.w + bL.w;
    h[4] += fdeg * cH.x + bH.x; h[5] += fdeg * cH.y + bH.y;
    h[6] += fdeg * cH.z + bH.z; h[7] += fdeg * cH.w + bH.w;

    float lg[4];
#pragma unroll
    for (int c = 0; c < 4; c++) {
        float ps = 0.f;
#pragma unroll
        for (int k = 0; k < 8; k++)
            ps = fmaf(h[k], __ldg(Wout + (sl * 8 + k) * 4 + c), ps);
        ps += __shfl_xor_sync(0xffffffffu, ps, 1);
        ps += __shfl_xor_sync(0xffffffffu, ps, 2);
        lg[c] = ps + __ldg(bout + c);
    }

    float m = fmaxf(fmaxf(lg[0], lg[1]), fmaxf(lg[2], lg[3]));
    float e0 = __expf(lg[0] - m);
    float e1 = __expf(lg[1] - m);
    float e2 = __expf(lg[2] - m);
    float e3 = __expf(lg[3] - m);
    float inv = 1.0f / (e0 + e1 + e2 + e3);
    if (sl == 0)
        *reinterpret_cast<float4*>(out + (size_t)node * 4) =
            make_float4(e0 * inv, e1 * inv, e2 * inv, e3 * inv);
}

// ---------------------------------------------------------------------------
// Launch.  Inputs: x, src, dst, w1, Wd1, b1, w2, Wd2, b2, Wout, bout
// Forked topology:
//   main:  wfrag -> dense ------\
//   side:  zero  -> fill  -------+--> gather1 -> gather2_final
// ---------------------------------------------------------------------------
extern "C" void kernel_launch(void* const* d_in, const int* in_sizes, int n_in,
                              void* d_out, int out_size) {
    const float* x    = (const float*)d_in[0];
    const int*   src  = (const int*)  d_in[1];
    const int*   dst  = (const int*)  d_in[2];
    const float* w1   = (const float*)d_in[3];
    const float* Wd1  = (const float*)d_in[4];
    const float* b1   = (const float*)d_in[5];
    const float* w2   = (const float*)d_in[6];
    const float* Wd2  = (const float*)d_in[7];
    const float* b2   = (const float*)d_in[8];
    const float* Wout = (const float*)d_in[9];
    const float* bout = (const float*)d_in[10];
    float* out = (float*)d_out;

    static cudaStream_t s2 = nullptr;
    static cudaEvent_t  e0 = nullptr, e1 = nullptr;
    if (s2 == nullptr) {
        cudaStreamCreateWithFlags(&s2, cudaStreamNonBlocking);
        cudaEventCreateWithFlags(&e0, cudaEventDisableTiming);
        cudaEventCreateWithFlags(&e1, cudaEventDisableTiming);
    }

    // fork: side stream builds adjacency while main stream projects x
    cudaEventRecord(e0, 0);
    cudaStreamWaitEvent(s2, e0, 0);
    k_zero<<<196, 256, 0, s2>>>();
    k_fill<<<586, 256, 0, s2>>>(src, dst);
    cudaEventRecord(e1, s2);

    k_wfrag<<<1, 1024>>>(w1, Wd1, w2, Wd2, b1);
    k_dense<<<782, 256>>>(x);

    // join: gather1 needs both dense (Z) and fill (buckets)
    cudaStreamWaitEvent(0, e1, 0);
    k_gather1<<<782, 256>>>();
    k_gather2_final<<<782, 256>>>(b2, Wout, bout, out);
}

// round 13
// speedup vs baseline: 1.3582x; 1.3582x over previous
#include <cuda_runtime.h>
#include <cuda_fp16.h>

#define NN 50000
#define NE 600000
#define CAP 64            // bucket capacity per node (max degree ~28)
#define SCALE 1024.0f
#define INV_SCALE (1.0f / 1024.0f)

// ---------------- scratch (__device__ globals) -----------------------------
__device__ __half g_Zh[NN * 32];     // fp16: x @ (S * D1 Wd1 D2 Wd2)
__device__ __half g_Th[NN * 32];     // fp16: A @ Z
__device__ int    g_deg[NN];
__device__ int    g_bucket[NN * CAP];
__device__ float  g_W12[128 * 32];        // collapsed weight (scaled)
__device__ uint2  g_WfragZ[8 * 4 * 32];   // collapsed-weight B fragments
__device__ float  g_c2[32];               // b1^T D2 Wd2

__device__ __forceinline__ unsigned s2u(const void* p) {
    return (unsigned)__cvta_generic_to_shared(p);
}
union H2U { __half2 h; unsigned u; };

// ---------------------------------------------------------------------------
__global__ void k_zero() {
    int i = blockIdx.x * 256 + threadIdx.x;
    if (i < NN) g_deg[i] = 0;
}

// ---------------------------------------------------------------------------
// k_w12: W12 = S * diag(w1) Wd1 diag(w2) Wd2   (128x32, fp32)
// 16 blocks x 256 threads; t2 = diag(w2)Wd2 staged in smem per block;
// one thread per (k, n) output, 64 smem FMAs.
// ---------------------------------------------------------------------------
__global__ void k_w12(const float* __restrict__ w1, const float* __restrict__ Wd1,
                      const float* __restrict__ w2, const float* __restrict__ Wd2) {
    __shared__ float t2[64 * 32];        // 8 KB
    int tid = threadIdx.x;
    for (int i = tid; i < 64 * 32; i += 256)
        t2[i] = w2[i >> 5] * Wd2[i];
    __syncthreads();

    int kl = tid >> 5;                   // 0..7
    int n  = tid & 31;
    int k  = blockIdx.x * 8 + kl;        // 0..127
    const float* wr = Wd1 + k * 64;
    float s = 0.f;
#pragma unroll 16
    for (int m = 0; m < 64; m++)
        s = fmaf(wr[m], t2[m * 32 + n], s);
    g_W12[k * 32 + n] = s * w1[k] * SCALE;
}

// ---------------------------------------------------------------------------
// k_wfrag: re-layout W12 into MMA B-fragments + compute c2 = b1^T D2 Wd2.
// 1 block x 1024 threads; pure gather/pack.
// ---------------------------------------------------------------------------
__global__ void k_wfrag(const float* __restrict__ w2, const float* __restrict__ Wd2,
                        const float* __restrict__ b1) {
    int i = threadIdx.x;                 // 0..1023
    int lane = i & 31, nt = (i >> 5) & 3, kt = i >> 7;
    int g = lane >> 2, tg = lane & 3;
    int n = nt * 8 + g;
    int k0 = kt * 16 + tg * 2;

    float v0 = g_W12[(k0    ) * 32 + n];
    float v1 = g_W12[(k0 + 1) * 32 + n];
    float v2 = g_W12[(k0 + 8) * 32 + n];
    float v3 = g_W12[(k0 + 9) * 32 + n];
    H2U u0, u1;
    u0.h = __floats2half2_rn(v0, v1);
    u1.h = __floats2half2_rn(v2, v3);
    g_WfragZ[i] = make_uint2(u0.u, u1.u);

    if (i < 32) {
        float s = 0.f;
#pragma unroll 16
        for (int m = 0; m < 64; m++)
            s = fmaf(b1[m] * w2[m], Wd2[m * 32 + i], s);
        g_c2[i] = s;
    }
}

// ---------------------------------------------------------------------------
// k_fill: one-pass adjacency build. deg doubles as cursor.
// ---------------------------------------------------------------------------
__global__ void k_fill(const int* __restrict__ src, const int* __restrict__ dst) {
    int i = blockIdx.x * 256 + threadIdx.x;
    if (i < NE / 4) {
        int4 s = reinterpret_cast<const int4*>(src)[i];
        int4 d = reinterpret_cast<const int4*>(dst)[i];
        int p;
        p = atomicAdd(&g_deg[d.x], 1); if (p < CAP) g_bucket[d.x * CAP + p] = s.x;
        p = atomicAdd(&g_deg[d.y], 1); if (p < CAP) g_bucket[d.y * CAP + p] = s.y;
        p = atomicAdd(&g_deg[d.z], 1); if (p < CAP) g_bucket[d.z * CAP + p] = s.z;
        p = atomicAdd(&g_deg[d.w], 1); if (p < CAP) g_bucket[d.w * CAP + p] = s.w;
    }
}

// ---------------------------------------------------------------------------
// k_dense: Z = x @ W12s  (K=128 -> N=32), HMMA, 64-node tiles, 782 blocks.
// 8 warps = 4 row-tiles x 2 col-halves (nt pairs).
// ---------------------------------------------------------------------------
__global__ void __launch_bounds__(256)
k_dense(const float* __restrict__ x) {
    __shared__ __half As[64 * 136];      // 17408 B
    int tid = threadIdx.x;
    int node0 = blockIdx.x * 64;
    for (int i = tid; i < 64 * 32; i += 256) {
        int r = i >> 5, c4 = i & 31;
        float4 v = make_float4(0.f, 0.f, 0.f, 0.f);
        if (node0 + r < NN)
            v = *reinterpret_cast<const float4*>(x + (size_t)(node0 + r) * 128 + c4 * 4);
        H2U u0, u1;
        u0.h = __floats2half2_rn(v.x, v.y);
        u1.h = __floats2half2_rn(v.z, v.w);
        *reinterpret_cast<uint2*>(As + r * 136 + c4 * 4) = make_uint2(u0.u, u1.u);
    }
    __syncthreads();

    int w = tid >> 5, lane = tid & 31, g = lane >> 2, tg = lane & 3;
    int warpRow = (w >> 1) * 16;
    int nthalf  = (w & 1) * 2;           // nt 0..1 or 2..3
    int lrow = warpRow + (lane & 15);
    int lkof = (lane >> 4) * 8;

    float acc[2][4] = {};
#pragma unroll
    for (int kt = 0; kt < 8; kt++) {
        unsigned a0, a1, a2, a3;
        unsigned addr = s2u(As + lrow * 136 + kt * 16 + lkof);
        asm volatile("ldmatrix.sync.aligned.m8n8.x4.shared.b16 {%0,%1,%2,%3}, [%4];"
                     : "=r"(a0), "=r"(a1), "=r"(a2), "=r"(a3) : "r"(addr));
#pragma unroll
        for (int nt = 0; nt < 2; nt++) {
            uint2 bb = __ldg(&g_WfragZ[((kt << 2) + nthalf + nt) * 32 + lane]);
            asm volatile(
                "mma.sync.aligned.m16n8k16.row.col.f32.f16.f16.f32 "
                "{%0,%1,%2,%3}, {%4,%5,%6,%7}, {%8,%9}, {%0,%1,%2,%3};"
                : "+f"(acc[nt][0]), "+f"(acc[nt][1]), "+f"(acc[nt][2]), "+f"(acc[nt][3])
                : "r"(a0), "r"(a1), "r"(a2), "r"(a3), "r"(bb.x), "r"(bb.y));
        }
    }

    int r0 = node0 + warpRow + g;
    int r1 = r0 + 8;
#pragma unroll
    for (int nt = 0; nt < 2; nt++) {
        int c = (nthalf + nt) * 8 + tg * 2;
        if (r0 < NN) {
            H2U u; u.h = __floats2half2_rn(acc[nt][0], acc[nt][1]);
            *reinterpret_cast<unsigned*>(g_Zh + (size_t)r0 * 32 + c) = u.u;
        }
        if (r1 < NN) {
            H2U u; u.h = __floats2half2_rn(acc[nt][2], acc[nt][3]);
            *reinterpret_cast<unsigned*>(g_Zh + (size_t)r1 * 32 + c) = u.u;
        }
    }
}

// ---------------------------------------------------------------------------
// half2 accumulation helper
// ---------------------------------------------------------------------------
__device__ __forceinline__ void hacc(__half2 a[4], uint4 v) {
    __half2* h = reinterpret_cast<__half2*>(&v);
    a[0] = __hadd2(a[0], h[0]);
    a[1] = __hadd2(a[1], h[1]);
    a[2] = __hadd2(a[2], h[2]);
    a[3] = __hadd2(a[3], h[3]);
}

// ---------------------------------------------------------------------------
// gather1: T = A@Z  (32-dim). 8 nodes/warp, 4 lanes x 8 halves.
// ---------------------------------------------------------------------------
__global__ void __launch_bounds__(256)
k_gather1() {
    int gw = (blockIdx.x * 256 + threadIdx.x) >> 5;
    int lane = threadIdx.x & 31;
    int sub = lane >> 2, sl = lane & 3;
    int node = gw * 8 + sub;
    if (node >= NN) return;

    int n = g_deg[node]; if (n > CAP) n = CAP;
    const int* bkt = g_bucket + (size_t)node * CAP;
    __half2 z = __float2half2_rn(0.f);
    __half2 s0[4] = {z, z, z, z}, s1[4] = {z, z, z, z};
    __half2 s2[4] = {z, z, z, z}, s3[4] = {z, z, z, z};

    int j = 0;
    for (; j + 4 <= n; j += 4) {
        int4 idx = *reinterpret_cast<const int4*>(bkt + j);
        hacc(s0, *reinterpret_cast<const uint4*>(g_Zh + (size_t)idx.x * 32 + sl * 8));
        hacc(s1, *reinterpret_cast<const uint4*>(g_Zh + (size_t)idx.y * 32 + sl * 8));
        hacc(s2, *reinterpret_cast<const uint4*>(g_Zh + (size_t)idx.z * 32 + sl * 8));
        hacc(s3, *reinterpret_cast<const uint4*>(g_Zh + (size_t)idx.w * 32 + sl * 8));
    }
    for (; j < n; j++)
        hacc(s0, *reinterpret_cast<const uint4*>(g_Zh + (size_t)bkt[j] * 32 + sl * 8));

    H2U p[4];
#pragma unroll
    for (int q = 0; q < 4; q++) {
        float2 f  = __half22float2(s0[q]);
        float2 t1 = __half22float2(s1[q]);
        float2 t2 = __half22float2(s2[q]);
        float2 t3 = __half22float2(s3[q]);
        p[q].h = __floats2half2_rn(f.x + t1.x + t2.x + t3.x,
                                   f.y + t1.y + t2.y + t3.y);
    }
    *reinterpret_cast<uint4*>(g_Th + (size_t)node * 32 + sl * 8) =
        make_uint4(p[0].u, p[1].u, p[2].u, p[3].u);
}

// ---------------------------------------------------------------------------
// gather2 + head + softmax.
// g2 = (A@T)/S + deg*c2 + b2;  logits = g2@Wout + bout; softmax.
// ---------------------------------------------------------------------------
__global__ void __launch_bounds__(256)
k_gather2_final(const float* __restrict__ b2,
                const float* __restrict__ Wout,
                const float* __restrict__ bout,
                float* __restrict__ out) {
    int gw = (blockIdx.x * 256 + threadIdx.x) >> 5;
    int lane = threadIdx.x & 31;
    int sub = lane >> 2, sl = lane & 3;
    int node = gw * 8 + sub;
    if (node >= NN) return;

    int deg = g_deg[node];
    int n = deg; if (n > CAP) n = CAP;
    const int* bkt = g_bucket + (size_t)node * CAP;
    __half2 z = __float2half2_rn(0.f);
    __half2 s0[4] = {z, z, z, z}, s1[4] = {z, z, z, z};
    __half2 s2[4] = {z, z, z, z}, s3[4] = {z, z, z, z};

    int j = 0;
    for (; j + 4 <= n; j += 4) {
        int4 idx = *reinterpret_cast<const int4*>(bkt + j);
        hacc(s0, *reinterpret_cast<const uint4*>(g_Th + (size_t)idx.x * 32 + sl * 8));
        hacc(s1, *reinterpret_cast<const uint4*>(g_Th + (size_t)idx.y * 32 + sl * 8));
        hacc(s2, *reinterpret_cast<const uint4*>(g_Th + (size_t)idx.z * 32 + sl * 8));
        hacc(s3, *reinterpret_cast<const uint4*>(g_Th + (size_t)idx.w * 32 + sl * 8));
    }
    for (; j < n; j++)
        hacc(s0, *reinterpret_cast<const uint4*>(g_Th + (size_t)bkt[j] * 32 + sl * 8));

    float fdeg = (float)deg;
    float4 bL = __ldg(reinterpret_cast<const float4*>(b2 + sl * 8));
    float4 bH = __ldg(reinterpret_cast<const float4*>(b2 + sl * 8 + 4));
    float4 cL = *reinterpret_cast<const float4*>(g_c2 + sl * 8);
    float4 cH = *reinterpret_cast<const float4*>(g_c2 + sl * 8 + 4);

    float h[8];
#pragma unroll
    for (int q = 0; q < 4; q++) {
        float2 f  = __half22float2(s0[q]);
        float2 t1 = __half22float2(s1[q]);
        float2 t2 = __half22float2(s2[q]);
        float2 t3 = __half22float2(s3[q]);
        h[q * 2]     = (f.x + t1.x + t2.x + t3.x) * INV_SCALE;
        h[q * 2 + 1] = (f.y + t1.y + t2.y + t3.y) * INV_SCALE;
    }
    h[0] += fdeg * cL.x + bL.x; h[1] += fdeg * cL.y + bL.y;
    h[2] += fdeg * cL.z + bL.z; h[3] += fdeg * cL.w + bL.w;
    h[4] += fdeg * cH.x + bH.x; h[5] += fdeg * cH.y + bH.y;
    h[6] += fdeg * cH.z + bH.z; h[7] += fdeg * cH.w + bH.w;

    float lg[4];
#pragma unroll
    for (int c = 0; c < 4; c++) {
        float ps = 0.f;
#pragma unroll
        for (int k = 0; k < 8; k++)
            ps = fmaf(h[k], __ldg(Wout + (sl * 8 + k) * 4 + c), ps);
        ps += __shfl_xor_sync(0xffffffffu, ps, 1);
        ps += __shfl_xor_sync(0xffffffffu, ps, 2);
        lg[c] = ps + __ldg(bout + c);
    }

    float m = fmaxf(fmaxf(lg[0], lg[1]), fmaxf(lg[2], lg[3]));
    float e0 = __expf(lg[0] - m);
    float e1 = __expf(lg[1] - m);
    float e2 = __expf(lg[2] - m);
    float e3 = __expf(lg[3] - m);
    float inv = 1.0f / (e0 + e1 + e2 + e3);
    if (sl == 0)
        *reinterpret_cast<float4*>(out + (size_t)node * 4) =
            make_float4(e0 * inv, e1 * inv, e2 * inv, e3 * inv);
}

// ---------------------------------------------------------------------------
// Launch.  Inputs: x, src, dst, w1, Wd1, b1, w2, Wd2, b2, Wout, bout
// Forked topology:
//   main:  w12 -> wfrag -> dense ---\
//   side:  zero -> fill  ------------+--> gather1 -> gather2_final
// ---------------------------------------------------------------------------
extern "C" void kernel_launch(void* const* d_in, const int* in_sizes, int n_in,
                              void* d_out, int out_size) {
    const float* x    = (const float*)d_in[0];
    const int*   src  = (const int*)  d_in[1];
    const int*   dst  = (const int*)  d_in[2];
    const float* w1   = (const float*)d_in[3];
    const float* Wd1  = (const float*)d_in[4];
    const float* b1   = (const float*)d_in[5];
    const float* w2   = (const float*)d_in[6];
    const float* Wd2  = (const float*)d_in[7];
    const float* b2   = (const float*)d_in[8];
    const float* Wout = (const float*)d_in[9];
    const float* bout = (const float*)d_in[10];
    float* out = (float*)d_out;

    static cudaStream_t s2 = nullptr;
    static cudaEvent_t  e0 = nullptr, e1 = nullptr;
    if (s2 == nullptr) {
        cudaStreamCreateWithFlags(&s2, cudaStreamNonBlocking);
        cudaEventCreateWithFlags(&e0, cudaEventDisableTiming);
        cudaEventCreateWithFlags(&e1, cudaEventDisableTiming);
    }

    // fork: side stream builds adjacency while main stream projects x
    cudaEventRecord(e0, 0);
    cudaStreamWaitEvent(s2, e0, 0);
    k_zero<<<196, 256, 0, s2>>>();
    k_fill<<<586, 256, 0, s2>>>(src, dst);
    cudaEventRecord(e1, s2);

    k_w12<<<16, 256>>>(w1, Wd1, w2, Wd2);
    k_wfrag<<<1, 1024>>>(w2, Wd2, b1);
    k_dense<<<782, 256>>>(x);

    // join: gather1 needs both dense (Z) and fill (buckets)
    cudaStreamWaitEvent(0, e1, 0);
    k_gather1<<<782, 256>>>();
    k_gather2_final<<<782, 256>>>(b2, Wout, bout, out);
}

// round 14
// speedup vs baseline: 1.4391x; 1.0596x over previous
#include <cuda_runtime.h>
#include <cuda_fp16.h>

#define NN 50000
#define NE 600000
#define CAP 64            // bucket capacity per node (max degree ~28)
#define SCALE 1024.0f
#define INV_SCALE (1.0f / 1024.0f)

// ---------------- scratch (__device__ globals) -----------------------------
__device__ __half g_Zh[NN * 32];     // fp16: x @ (S * D1 Wd1 D2 Wd2)
__device__ __half g_Th[NN * 32];     // fp16: A @ Z
__device__ int    g_deg[NN];
__device__ int    g_bucket[NN * CAP];
__device__ uint2  g_WfragZ[8 * 4 * 32];   // collapsed-weight B fragments
__device__ float  g_c2[32];               // b1^T D2 Wd2

__device__ __forceinline__ unsigned s2u(const void* p) {
    return (unsigned)__cvta_generic_to_shared(p);
}
union H2U { __half2 h; unsigned u; };

// ---------------------------------------------------------------------------
__global__ void k_zero() {
    int i = blockIdx.x * 256 + threadIdx.x;
    if (i < NN) g_deg[i] = 0;
}

// ---------------------------------------------------------------------------
// k_w12frag: W12 = S * diag(w1) Wd1 diag(w2) Wd2, scattered DIRECTLY into
// MMA B-fragment half-slots.  16 blocks x 256 threads, one thread per (k,n).
// Block 0 also computes c2 = b1^T diag(w2) Wd2 from the staged t2 tile.
// ---------------------------------------------------------------------------
__global__ void k_w12frag(const float* __restrict__ w1, const float* __restrict__ Wd1,
                          const float* __restrict__ w2, const float* __restrict__ Wd2,
                          const float* __restrict__ b1) {
    __shared__ float t2[64 * 32];        // 8 KB: diag(w2) Wd2
    int tid = threadIdx.x;
    for (int i = tid; i < 64 * 32; i += 256)
        t2[i] = w2[i >> 5] * Wd2[i];
    __syncthreads();

    int kl = tid >> 5;                   // 0..7
    int n  = tid & 31;
    int k  = blockIdx.x * 8 + kl;        // 0..127
    const float* wr = Wd1 + k * 64;
    float s = 0.f;
#pragma unroll 16
    for (int m = 0; m < 64; m++)
        s = fmaf(wr[m], t2[m * 32 + n], s);
    s *= w1[k] * SCALE;

    // scatter straight into fragment layout:
    //   kt=k>>4, r=k&15  ->  tg=(r&7)>>1, q=((r>>3)<<1)|(r&1)
    //   nt=n>>3, g=n&7   ->  lane=(g<<2)|tg
    int kt = k >> 4, r = k & 15;
    int tg = (r & 7) >> 1;
    int q  = ((r >> 3) << 1) | (r & 1);
    int g  = n & 7, nt = n >> 3;
    int lane = (g << 2) | tg;
    int idx  = ((kt << 2) + nt) * 32 + lane;
    reinterpret_cast<__half*>(g_WfragZ)[idx * 4 + q] = __float2half(s);

    if (blockIdx.x == 0 && tid < 32) {
        float c = 0.f;
#pragma unroll 16
        for (int m = 0; m < 64; m++)
            c = fmaf(b1[m], t2[m * 32 + tid], c);
        g_c2[tid] = c;
    }
}

// ---------------------------------------------------------------------------
// k_fill: one-pass adjacency build. deg doubles as cursor.
// ---------------------------------------------------------------------------
__global__ void k_fill(const int* __restrict__ src, const int* __restrict__ dst) {
    int i = blockIdx.x * 256 + threadIdx.x;
    if (i < NE / 4) {
        int4 s = reinterpret_cast<const int4*>(src)[i];
        int4 d = reinterpret_cast<const int4*>(dst)[i];
        int p;
        p = atomicAdd(&g_deg[d.x], 1); if (p < CAP) g_bucket[d.x * CAP + p] = s.x;
        p = atomicAdd(&g_deg[d.y], 1); if (p < CAP) g_bucket[d.y * CAP + p] = s.y;
        p = atomicAdd(&g_deg[d.z], 1); if (p < CAP) g_bucket[d.z * CAP + p] = s.z;
        p = atomicAdd(&g_deg[d.w], 1); if (p < CAP) g_bucket[d.w * CAP + p] = s.w;
    }
}

// ---------------------------------------------------------------------------
// k_dense: Z = x @ W12s  (K=128 -> N=32), HMMA, 64-node tiles, 782 blocks.
// ---------------------------------------------------------------------------
__global__ void __launch_bounds__(256)
k_dense(const float* __restrict__ x) {
    __shared__ __half As[64 * 136];      // 17408 B
    int tid = threadIdx.x;
    int node0 = blockIdx.x * 64;
    for (int i = tid; i < 64 * 32; i += 256) {
        int r = i >> 5, c4 = i & 31;
        float4 v = make_float4(0.f, 0.f, 0.f, 0.f);
        if (node0 + r < NN)
            v = *reinterpret_cast<const float4*>(x + (size_t)(node0 + r) * 128 + c4 * 4);
        H2U u0, u1;
        u0.h = __floats2half2_rn(v.x, v.y);
        u1.h = __floats2half2_rn(v.z, v.w);
        *reinterpret_cast<uint2*>(As + r * 136 + c4 * 4) = make_uint2(u0.u, u1.u);
    }
    __syncthreads();

    int w = tid >> 5, lane = tid & 31, g = lane >> 2, tg = lane & 3;
    int warpRow = (w >> 1) * 16;
    int nthalf  = (w & 1) * 2;           // nt 0..1 or 2..3
    int lrow = warpRow + (lane & 15);
    int lkof = (lane >> 4) * 8;

    float acc[2][4] = {};
#pragma unroll
    for (int kt = 0; kt < 8; kt++) {
        unsigned a0, a1, a2, a3;
        unsigned addr = s2u(As + lrow * 136 + kt * 16 + lkof);
        asm volatile("ldmatrix.sync.aligned.m8n8.x4.shared.b16 {%0,%1,%2,%3}, [%4];"
                     : "=r"(a0), "=r"(a1), "=r"(a2), "=r"(a3) : "r"(addr));
#pragma unroll
        for (int nt = 0; nt < 2; nt++) {
            uint2 bb = __ldg(&g_WfragZ[((kt << 2) + nthalf + nt) * 32 + lane]);
            asm volatile(
                "mma.sync.aligned.m16n8k16.row.col.f32.f16.f16.f32 "
                "{%0,%1,%2,%3}, {%4,%5,%6,%7}, {%8,%9}, {%0,%1,%2,%3};"
                : "+f"(acc[nt][0]), "+f"(acc[nt][1]), "+f"(acc[nt][2]), "+f"(acc[nt][3])
                : "r"(a0), "r"(a1), "r"(a2), "r"(a3), "r"(bb.x), "r"(bb.y));
        }
    }

    int r0 = node0 + warpRow + g;
    int r1 = r0 + 8;
#pragma unroll
    for (int nt = 0; nt < 2; nt++) {
        int c = (nthalf + nt) * 8 + tg * 2;
        if (r0 < NN) {
            H2U u; u.h = __floats2half2_rn(acc[nt][0], acc[nt][1]);
            *reinterpret_cast<unsigned*>(g_Zh + (size_t)r0 * 32 + c) = u.u;
        }
        if (r1 < NN) {
            H2U u; u.h = __floats2half2_rn(acc[nt][2], acc[nt][3]);
            *reinterpret_cast<unsigned*>(g_Zh + (size_t)r1 * 32 + c) = u.u;
        }
    }
}

// ---------------------------------------------------------------------------
// half2 accumulation helper
// ---------------------------------------------------------------------------
__device__ __forceinline__ void hacc(__half2 a[4], uint4 v) {
    __half2* h = reinterpret_cast<__half2*>(&v);
    a[0] = __hadd2(a[0], h[0]);
    a[1] = __hadd2(a[1], h[1]);
    a[2] = __hadd2(a[2], h[2]);
    a[3] = __hadd2(a[3], h[3]);
}

// ---------------------------------------------------------------------------
// gather1: T = A@Z  (32-dim). 8 nodes/warp, 4 lanes x 8 halves.
// ---------------------------------------------------------------------------
__global__ void __launch_bounds__(256)
k_gather1() {
    int gw = (blockIdx.x * 256 + threadIdx.x) >> 5;
    int lane = threadIdx.x & 31;
    int sub = lane >> 2, sl = lane & 3;
    int node = gw * 8 + sub;
    if (node >= NN) return;

    int n = g_deg[node]; if (n > CAP) n = CAP;
    const int* bkt = g_bucket + (size_t)node * CAP;
    __half2 z = __float2half2_rn(0.f);
    __half2 s0[4] = {z, z, z, z}, s1[4] = {z, z, z, z};
    __half2 s2[4] = {z, z, z, z}, s3[4] = {z, z, z, z};

    int j = 0;
    for (; j + 4 <= n; j += 4) {
        int4 idx = *reinterpret_cast<const int4*>(bkt + j);
        hacc(s0, *reinterpret_cast<const uint4*>(g_Zh + (size_t)idx.x * 32 + sl * 8));
        hacc(s1, *reinterpret_cast<const uint4*>(g_Zh + (size_t)idx.y * 32 + sl * 8));
        hacc(s2, *reinterpret_cast<const uint4*>(g_Zh + (size_t)idx.z * 32 + sl * 8));
        hacc(s3, *reinterpret_cast<const uint4*>(g_Zh + (size_t)idx.w * 32 + sl * 8));
    }
    for (; j < n; j++)
        hacc(s0, *reinterpret_cast<const uint4*>(g_Zh + (size_t)bkt[j] * 32 + sl * 8));

    H2U p[4];
#pragma unroll
    for (int q = 0; q < 4; q++) {
        float2 f  = __half22float2(s0[q]);
        float2 t1 = __half22float2(s1[q]);
        float2 t2 = __half22float2(s2[q]);
        float2 t3 = __half22float2(s3[q]);
        p[q].h = __floats2half2_rn(f.x + t1.x + t2.x + t3.x,
                                   f.y + t1.y + t2.y + t3.y);
    }
    *reinterpret_cast<uint4*>(g_Th + (size_t)node * 32 + sl * 8) =
        make_uint4(p[0].u, p[1].u, p[2].u, p[3].u);
}

// ---------------------------------------------------------------------------
// gather2 + head + softmax.
// g2 = (A@T)/S + deg*c2 + b2;  logits = g2@Wout + bout; softmax.
// ---------------------------------------------------------------------------
__global__ void __launch_bounds__(256)
k_gather2_final(const float* __restrict__ b2,
                const float* __restrict__ Wout,
                const float* __restrict__ bout,
                float* __restrict__ out) {
    int gw = (blockIdx.x * 256 + threadIdx.x) >> 5;
    int lane = threadIdx.x & 31;
    int sub = lane >> 2, sl = lane & 3;
    int node = gw * 8 + sub;
    if (node >= NN) return;

    int deg = g_deg[node];
    int n = deg; if (n > CAP) n = CAP;
    const int* bkt = g_bucket + (size_t)node * CAP;
    __half2 z = __float2half2_rn(0.f);
    __half2 s0[4] = {z, z, z, z}, s1[4] = {z, z, z, z};
    __half2 s2[4] = {z, z, z, z}, s3[4] = {z, z, z, z};

    int j = 0;
    for (; j + 4 <= n; j += 4) {
        int4 idx = *reinterpret_cast<const int4*>(bkt + j);
        hacc(s0, *reinterpret_cast<const uint4*>(g_Th + (size_t)idx.x * 32 + sl * 8));
        hacc(s1, *reinterpret_cast<const uint4*>(g_Th + (size_t)idx.y * 32 + sl * 8));
        hacc(s2, *reinterpret_cast<const uint4*>(g_Th + (size_t)idx.z * 32 + sl * 8));
        hacc(s3, *reinterpret_cast<const uint4*>(g_Th + (size_t)idx.w * 32 + sl * 8));
    }
    for (; j < n; j++)
        hacc(s0, *reinterpret_cast<const uint4*>(g_Th + (size_t)bkt[j] * 32 + sl * 8));

    float fdeg = (float)deg;
    float4 bL = __ldg(reinterpret_cast<const float4*>(b2 + sl * 8));
    float4 bH = __ldg(reinterpret_cast<const float4*>(b2 + sl * 8 + 4));
    float4 cL = *reinterpret_cast<const float4*>(g_c2 + sl * 8);
    float4 cH = *reinterpret_cast<const float4*>(g_c2 + sl * 8 + 4);

    float h[8];
#pragma unroll
    for (int q = 0; q < 4; q++) {
        float2 f  = __half22float2(s0[q]);
        float2 t1 = __half22float2(s1[q]);
        float2 t2 = __half22float2(s2[q]);
        float2 t3 = __half22float2(s3[q]);
        h[q * 2]     = (f.x + t1.x + t2.x + t3.x) * INV_SCALE;
        h[q * 2 + 1] = (f.y + t1.y + t2.y + t3.y) * INV_SCALE;
    }
    h[0] += fdeg * cL.x + bL.x; h[1] += fdeg * cL.y + bL.y;
    h[2] += fdeg * cL.z + bL.z; h[3] += fdeg * cL.w + bL.w;
    h[4] += fdeg * cH.x + bH.x; h[5] += fdeg * cH.y + bH.y;
    h[6] += fdeg * cH.z + bH.z; h[7] += fdeg * cH.w + bH.w;

    float lg[4];
#pragma unroll
    for (int c = 0; c < 4; c++) {
        float ps = 0.f;
#pragma unroll
        for (int k = 0; k < 8; k++)
            ps = fmaf(h[k], __ldg(Wout + (sl * 8 + k) * 4 + c), ps);
        ps += __shfl_xor_sync(0xffffffffu, ps, 1);
        ps += __shfl_xor_sync(0xffffffffu, ps, 2);
        lg[c] = ps + __ldg(bout + c);
    }

    float m = fmaxf(fmaxf(lg[0], lg[1]), fmaxf(lg[2], lg[3]));
    float e0 = __expf(lg[0] - m);
    float e1 = __expf(lg[1] - m);
    float e2 = __expf(lg[2] - m);
    float e3 = __expf(lg[3] - m);
    float inv = 1.0f / (e0 + e1 + e2 + e3);
    if (sl == 0)
        *reinterpret_cast<float4*>(out + (size_t)node * 4) =
            make_float4(e0 * inv, e1 * inv, e2 * inv, e3 * inv);
}

// ---------------------------------------------------------------------------
// Launch.  Inputs: x, src, dst, w1, Wd1, b1, w2, Wd2, b2, Wout, bout
// Forked topology:
//   main:  w12frag -> dense ---\
//   side:  zero -> fill  -------+--> gather1 -> gather2_final
// ---------------------------------------------------------------------------
extern "C" void kernel_launch(void* const* d_in, const int* in_sizes, int n_in,
                              void* d_out, int out_size) {
    const float* x    = (const float*)d_in[0];
    const int*   src  = (const int*)  d_in[1];
    const int*   dst  = (const int*)  d_in[2];
    const float* w1   = (const float*)d_in[3];
    const float* Wd1  = (const float*)d_in[4];
    const float* b1   = (const float*)d_in[5];
    const float* w2   = (const float*)d_in[6];
    const float* Wd2  = (const float*)d_in[7];
    const float* b2   = (const float*)d_in[8];
    const float* Wout = (const float*)d_in[9];
    const float* bout = (const float*)d_in[10];
    float* out = (float*)d_out;

    static cudaStream_t s2 = nullptr;
    static cudaEvent_t  e0 = nullptr, e1 = nullptr;
    if (s2 == nullptr) {
        cudaStreamCreateWithFlags(&s2, cudaStreamNonBlocking);
        cudaEventCreateWithFlags(&e0, cudaEventDisableTiming);
        cudaEventCreateWithFlags(&e1, cudaEventDisableTiming);
    }

    // fork: side stream builds adjacency while main stream projects x
    cudaEventRecord(e0, 0);
    cudaStreamWaitEvent(s2, e0, 0);
    k_zero<<<196, 256, 0, s2>>>();
    k_fill<<<586, 256, 0, s2>>>(src, dst);
    cudaEventRecord(e1, s2);

    k_w12frag<<<16, 256>>>(w1, Wd1, w2, Wd2, b1);
    k_dense<<<782, 256>>>(x);

    // join: gather1 needs both dense (Z) and fill (buckets)
    cudaStreamWaitEvent(0, e1, 0);
    k_gather1<<<782, 256>>>();
    k_gather2_final<<<782, 256>>>(b2, Wout, bout, out);
}